// round 1
// baseline (speedup 1.0000x reference)
#include <cuda_runtime.h>
#include <math.h>

#define BB   2
#define TT   1024
#define EE   1024
#define HH   16
#define HD   64
#define LL   8
#define FF_  4096
#define VV   32000
#define MROWS (BB*TT)          // 2048

// ---------------- scratch (no allocation allowed -> __device__ globals) ----------------
__device__ float g_x  [MROWS*EE];
__device__ float g_h  [MROWS*EE];
__device__ float g_q  [MROWS*EE];
__device__ float g_k  [MROWS*EE];
__device__ float g_v  [MROWS*EE];
__device__ float g_o  [MROWS*EE];
__device__ float g_ff [MROWS*FF_];
__device__ float g_att[BB*HH*TT*TT];   // 128 MB scores/probs
__device__ float g_rowloss[MROWS];

// ---------------- embedding ----------------
__global__ void embed_kernel(const int* __restrict__ ctx, const float* __restrict__ tok,
                             const float* __restrict__ pos, float* __restrict__ x)
{
    int row = blockIdx.x;            // 0..MROWS-1
    int t   = row % TT;
    int token = ctx[row];
    const float* te = tok + (size_t)token * EE;
    const float* pe = pos + (size_t)t * EE;
    float* xr = x + (size_t)row * EE;
    for (int e = threadIdx.x; e < EE; e += blockDim.x)
        xr[e] = te[e] + pe[e];
}

// ---------------- layernorm (one block per row) ----------------
__global__ void ln_kernel(const float* __restrict__ x, const float* __restrict__ g,
                          const float* __restrict__ b, float* __restrict__ y)
{
    int row = blockIdx.x;
    const float* xr = x + (size_t)row * EE;
    float* yr = y + (size_t)row * EE;
    __shared__ float red[256];
    int tid = threadIdx.x;

    float s = 0.f;
    for (int i = tid; i < EE; i += 256) s += xr[i];
    red[tid] = s; __syncthreads();
    for (int o = 128; o > 0; o >>= 1) { if (tid < o) red[tid] += red[tid + o]; __syncthreads(); }
    float mu = red[0] * (1.0f / EE);
    __syncthreads();

    float v = 0.f;
    for (int i = tid; i < EE; i += 256) { float d = xr[i] - mu; v += d * d; }
    red[tid] = v; __syncthreads();
    for (int o = 128; o > 0; o >>= 1) { if (tid < o) red[tid] += red[tid + o]; __syncthreads(); }
    float rstd = rsqrtf(red[0] * (1.0f / EE) + 1e-5f);

    for (int i = tid; i < EE; i += 256)
        yr[i] = (xr[i] - mu) * rstd * g[i] + b[i];
}

// ---------------- SGEMM: C[M,N] = A[M,K] @ W[K,N] (+bias)(+res)(relu?) ----------------
// BM=BN=128, BK=8, 256 threads, 8x8 microtile. Requires M%128==0, N%128==0, K%8==0.
__global__ __launch_bounds__(256) void sgemm_kernel(
    const float* __restrict__ A, const float* __restrict__ W,
    const float* __restrict__ bias, const float* __restrict__ res,
    float* __restrict__ C, int M, int N, int K, int relu)
{
    __shared__ float As[8][128];
    __shared__ float Bs[8][132];

    int tid  = threadIdx.x;
    int row0 = blockIdx.y * 128;
    int col0 = blockIdx.x * 128;
    int tx = tid & 15, ty = tid >> 4;

    int a_row = tid >> 1;          // 0..127
    int a_col = (tid & 1) * 4;     // 0 / 4
    int b_row = tid >> 5;          // 0..7
    int b_col = (tid & 31) * 4;    // 0..124

    float acc[8][8];
    #pragma unroll
    for (int i = 0; i < 8; i++)
        #pragma unroll
        for (int j = 0; j < 8; j++) acc[i][j] = 0.f;

    const float* Aptr = A + (size_t)(row0 + a_row) * K + a_col;
    const float* Wptr = W + (size_t)b_row * N + col0 + b_col;

    for (int k0 = 0; k0 < K; k0 += 8) {
        float4 av = *(const float4*)(Aptr + k0);
        As[a_col + 0][a_row] = av.x;
        As[a_col + 1][a_row] = av.y;
        As[a_col + 2][a_row] = av.z;
        As[a_col + 3][a_row] = av.w;
        float4 bv = *(const float4*)(Wptr + (size_t)k0 * N);
        *(float4*)&Bs[b_row][b_col] = bv;
        __syncthreads();

        #pragma unroll
        for (int kk = 0; kk < 8; kk++) {
            float4 a0 = *(const float4*)&As[kk][ty * 8];
            float4 a1 = *(const float4*)&As[kk][ty * 8 + 4];
            float4 b0 = *(const float4*)&Bs[kk][tx * 8];
            float4 b1 = *(const float4*)&Bs[kk][tx * 8 + 4];
            float ar[8] = {a0.x,a0.y,a0.z,a0.w,a1.x,a1.y,a1.z,a1.w};
            float br[8] = {b0.x,b0.y,b0.z,b0.w,b1.x,b1.y,b1.z,b1.w};
            #pragma unroll
            for (int i = 0; i < 8; i++)
                #pragma unroll
                for (int j = 0; j < 8; j++) acc[i][j] += ar[i] * br[j];
        }
        __syncthreads();
    }

    #pragma unroll
    for (int i = 0; i < 8; i++) {
        int r = row0 + ty * 8 + i;
        #pragma unroll
        for (int j = 0; j < 8; j++) {
            int c = col0 + tx * 8 + j;
            float val = acc[i][j];
            if (bias) val += bias[c];
            if (res)  val += res[(size_t)r * N + c];
            if (relu) val = fmaxf(val, 0.f);
            C[(size_t)r * N + c] = val;
        }
    }
}

// ---------------- attention scores: S[bh,q,k] = (Q.K)/32 ----------------
__global__ __launch_bounds__(256) void attn_scores_kernel(
    const float* __restrict__ q, const float* __restrict__ k, float* __restrict__ att)
{
    int kt = blockIdx.x, qt = blockIdx.y, bh = blockIdx.z;
    if (kt > qt) return;                         // causal pruning at tile level
    int b = bh / HH, h = bh % HH;
    int q0 = qt * 64, k0 = kt * 64;

    __shared__ float Qs[64][65];
    __shared__ float Ks[64][65];
    int tid = threadIdx.x;
    for (int i = tid; i < 64 * 64; i += 256) {
        int r = i >> 6, d = i & 63;
        Qs[r][d] = q[(size_t)(b * TT + q0 + r) * EE + h * 64 + d];
        Ks[r][d] = k[(size_t)(b * TT + k0 + r) * EE + h * 64 + d];
    }
    __syncthreads();

    int tx = tid & 15, ty = tid >> 4;
    float acc[4][4] = {};
    #pragma unroll 4
    for (int d = 0; d < 64; d++) {
        float ar[4], br[4];
        #pragma unroll
        for (int i = 0; i < 4; i++) ar[i] = Qs[ty * 4 + i][d];
        #pragma unroll
        for (int j = 0; j < 4; j++) br[j] = Ks[tx * 4 + j][d];
        #pragma unroll
        for (int i = 0; i < 4; i++)
            #pragma unroll
            for (int j = 0; j < 4; j++) acc[i][j] += ar[i] * br[j];
    }
    const float scale = 0.03125f;  // 1/sqrt(E) = 1/32
    #pragma unroll
    for (int i = 0; i < 4; i++)
        #pragma unroll
        for (int j = 0; j < 4; j++)
            att[((size_t)bh * TT + q0 + ty * 4 + i) * TT + k0 + tx * 4 + j] = acc[i][j] * scale;
}

// ---------------- causal softmax (one block per (bh,q) row) ----------------
__global__ void softmax_kernel(float* __restrict__ att)
{
    int row  = blockIdx.x;          // bh*TT + q
    int qpos = row % TT;
    float* p = att + (size_t)row * TT;
    int n = qpos + 1;
    __shared__ float red[256];
    int tid = threadIdx.x;

    float m = -1e30f;
    for (int i = tid; i < n; i += 256) m = fmaxf(m, p[i]);
    red[tid] = m; __syncthreads();
    for (int o = 128; o > 0; o >>= 1) { if (tid < o) red[tid] = fmaxf(red[tid], red[tid + o]); __syncthreads(); }
    m = red[0]; __syncthreads();

    float s = 0.f;
    for (int i = tid; i < n; i += 256) s += expf(p[i] - m);
    red[tid] = s; __syncthreads();
    for (int o = 128; o > 0; o >>= 1) { if (tid < o) red[tid] += red[tid + o]; __syncthreads(); }
    float inv = 1.f / red[0];

    for (int i = tid; i < n; i += 256) p[i] = expf(p[i] - m) * inv;
    for (int i = n + tid; i < TT; i += 256) p[i] = 0.f;
}

// ---------------- O = P @ V (per (bh, 64-q tile)) ----------------
__global__ __launch_bounds__(256) void attn_o_kernel(
    const float* __restrict__ att, const float* __restrict__ v, float* __restrict__ o)
{
    int qt = blockIdx.x, bh = blockIdx.y;
    int b = bh / HH, h = bh % HH;
    int q0 = qt * 64;

    __shared__ float Ps[64][65];
    __shared__ float Vs[64][65];
    int tid = threadIdx.x, tx = tid & 15, ty = tid >> 4;
    float acc[4][4] = {};

    for (int kt = 0; kt <= qt; kt++) {
        int k0 = kt * 64;
        for (int i = tid; i < 64 * 64; i += 256) {
            int r = i >> 6, c = i & 63;
            Ps[r][c] = att[((size_t)bh * TT + q0 + r) * TT + k0 + c];
            Vs[r][c] = v[(size_t)(b * TT + k0 + r) * EE + h * 64 + c];
        }
        __syncthreads();
        #pragma unroll 4
        for (int kk = 0; kk < 64; kk++) {
            float ar[4], br[4];
            #pragma unroll
            for (int i = 0; i < 4; i++) ar[i] = Ps[ty * 4 + i][kk];
            #pragma unroll
            for (int j = 0; j < 4; j++) br[j] = Vs[kk][tx * 4 + j];
            #pragma unroll
            for (int i = 0; i < 4; i++)
                #pragma unroll
                for (int j = 0; j < 4; j++) acc[i][j] += ar[i] * br[j];
        }
        __syncthreads();
    }
    #pragma unroll
    for (int i = 0; i < 4; i++)
        #pragma unroll
        for (int j = 0; j < 4; j++)
            o[(size_t)(b * TT + q0 + ty * 4 + i) * EE + h * 64 + tx * 4 + j] = acc[i][j];
}

// ---------------- cross-entropy: per-row lse - logit[target] ----------------
__global__ void loss_row_kernel(const float* __restrict__ logits, const int* __restrict__ targets,
                                float* __restrict__ rowloss)
{
    int row = blockIdx.x;
    const float* lr = logits + (size_t)row * VV;
    __shared__ float red[256];
    int tid = threadIdx.x;

    float m = -1e30f;
    for (int i = tid; i < VV; i += 256) m = fmaxf(m, lr[i]);
    red[tid] = m; __syncthreads();
    for (int o = 128; o > 0; o >>= 1) { if (tid < o) red[tid] = fmaxf(red[tid], red[tid + o]); __syncthreads(); }
    m = red[0]; __syncthreads();

    float s = 0.f;
    for (int i = tid; i < VV; i += 256) s += expf(lr[i] - m);
    red[tid] = s; __syncthreads();
    for (int o = 128; o > 0; o >>= 1) { if (tid < o) red[tid] += red[tid + o]; __syncthreads(); }

    if (tid == 0) {
        float lse = m + logf(red[0]);
        rowloss[row] = lse - lr[targets[row]];
    }
}

__global__ void loss_reduce_kernel(const float* __restrict__ rowloss, float* __restrict__ out)
{
    __shared__ float red[256];
    int tid = threadIdx.x;
    float s = 0.f;
    for (int i = tid; i < MROWS; i += 256) s += rowloss[i];
    red[tid] = s; __syncthreads();
    for (int o = 128; o > 0; o >>= 1) { if (tid < o) red[tid] += red[tid + o]; __syncthreads(); }
    if (tid == 0) out[0] = red[0] * (1.0f / MROWS);
}

// ---------------- host orchestration ----------------
extern "C" void kernel_launch(void* const* d_in, const int* in_sizes, int n_in,
                              void* d_out, int out_size)
{
    const int*   ctx  = (const int*)  d_in[0];
    const int*   tgt  = (const int*)  d_in[1];
    const float* tok  = (const float*)d_in[2];
    const float* pos  = (const float*)d_in[3];
    const float* Wq   = (const float*)d_in[4];
    const float* Wk   = (const float*)d_in[5];
    const float* Wv   = (const float*)d_in[6];
    const float* Wo   = (const float*)d_in[7];
    const float* bo   = (const float*)d_in[8];
    const float* ln1g = (const float*)d_in[9];
    const float* ln1b = (const float*)d_in[10];
    const float* ln2g = (const float*)d_in[11];
    const float* ln2b = (const float*)d_in[12];
    const float* W1   = (const float*)d_in[13];
    const float* b1   = (const float*)d_in[14];
    const float* W2   = (const float*)d_in[15];
    const float* b2   = (const float*)d_in[16];
    const float* lnfg = (const float*)d_in[17];
    const float* lnfb = (const float*)d_in[18];
    const float* Wlm  = (const float*)d_in[19];
    const float* blm  = (const float*)d_in[20];

    static float *px = nullptr, *ph, *pq, *pk, *pv, *po, *pff, *patt, *prl;
    if (!px) {
        cudaGetSymbolAddress((void**)&px,  g_x);
        cudaGetSymbolAddress((void**)&ph,  g_h);
        cudaGetSymbolAddress((void**)&pq,  g_q);
        cudaGetSymbolAddress((void**)&pk,  g_k);
        cudaGetSymbolAddress((void**)&pv,  g_v);
        cudaGetSymbolAddress((void**)&po,  g_o);
        cudaGetSymbolAddress((void**)&pff, g_ff);
        cudaGetSymbolAddress((void**)&patt, g_att);
        cudaGetSymbolAddress((void**)&prl, g_rowloss);
    }
    float* out = (float*)d_out;

    embed_kernel<<<MROWS, 256>>>(ctx, tok, pos, px);

    dim3 gE (EE  / 128, MROWS / 128);     // (8,16)
    dim3 gF (FF_ / 128, MROWS / 128);     // (32,16)
    dim3 gV (VV  / 128, MROWS / 128);     // (250,16)
    dim3 gS (TT / 64, TT / 64, BB * HH);  // (16,16,32)
    dim3 gO (TT / 64, BB * HH);           // (16,32)

    for (int l = 0; l < LL; l++) {
        ln_kernel<<<MROWS, 256>>>(px, ln1g + l * EE, ln1b + l * EE, ph);

        sgemm_kernel<<<gE, 256>>>(ph, Wq + (size_t)l * EE * EE, nullptr, nullptr, pq, MROWS, EE, EE, 0);
        sgemm_kernel<<<gE, 256>>>(ph, Wk + (size_t)l * EE * EE, nullptr, nullptr, pk, MROWS, EE, EE, 0);
        sgemm_kernel<<<gE, 256>>>(ph, Wv + (size_t)l * EE * EE, nullptr, nullptr, pv, MROWS, EE, EE, 0);

        attn_scores_kernel<<<gS, 256>>>(pq, pk, patt);
        softmax_kernel<<<BB * HH * TT, 256>>>(patt);
        attn_o_kernel<<<gO, 256>>>(patt, pv, po);

        sgemm_kernel<<<gE, 256>>>(po, Wo + (size_t)l * EE * EE, bo + l * EE, px, px, MROWS, EE, EE, 0);

        ln_kernel<<<MROWS, 256>>>(px, ln2g + l * EE, ln2b + l * EE, ph);
        sgemm_kernel<<<gF, 256>>>(ph, W1 + (size_t)l * EE * FF_, b1 + l * FF_, nullptr, pff, MROWS, FF_, EE, 1);
        sgemm_kernel<<<gE, 256>>>(pff, W2 + (size_t)l * FF_ * EE, b2 + l * EE, px, px, MROWS, EE, FF_, 0);
    }

    ln_kernel<<<MROWS, 256>>>(px, lnfg, lnfb, ph);
    sgemm_kernel<<<gV, 256>>>(ph, Wlm, blm, nullptr, out, MROWS, VV, EE, 0);

    if (out_size > MROWS * VV) {
        loss_row_kernel<<<MROWS, 256>>>(out, tgt, prl);
        loss_reduce_kernel<<<1, 256>>>(prl, out + (size_t)MROWS * VV);
    }
}

// round 2
// speedup vs baseline: 2.7015x; 2.7015x over previous
#include <cuda_runtime.h>
#include <math.h>
#include <stdint.h>

#define BB   2
#define TT   1024
#define EE   1024
#define HH   16
#define HD   64
#define LL   8
#define FF_  4096
#define VV   32000
#define MROWS (BB*TT)          // 2048

// ---------------- scratch (no allocation allowed -> __device__ globals) ----------------
__device__ float g_x  [MROWS*EE];
__device__ float g_h  [MROWS*EE];
__device__ float g_q  [MROWS*EE];
__device__ float g_k  [MROWS*EE];
__device__ float g_v  [MROWS*EE];
__device__ float g_o  [MROWS*EE];
__device__ float g_ff [MROWS*FF_];
__device__ float g_att[BB*HH*TT*TT];   // 128 MB scores/probs
__device__ float g_rowloss[MROWS];

// ---------------- helpers ----------------
__device__ __forceinline__ float f2tf32(float x) {
    uint32_t u;
    asm("cvt.rna.tf32.f32 %0, %1;" : "=r"(u) : "f"(x));
    return __uint_as_float(u);
}

__device__ __forceinline__ void mma_tf32(float* d, const uint32_t* a, const uint32_t* b) {
    asm volatile(
        "mma.sync.aligned.m16n8k8.row.col.f32.tf32.tf32.f32 "
        "{%0,%1,%2,%3}, {%4,%5,%6,%7}, {%8,%9}, {%0,%1,%2,%3};"
        : "+f"(d[0]), "+f"(d[1]), "+f"(d[2]), "+f"(d[3])
        : "r"(a[0]), "r"(a[1]), "r"(a[2]), "r"(a[3]), "r"(b[0]), "r"(b[1]));
}

// ---------------- embedding ----------------
__global__ void embed_kernel(const int* __restrict__ ctx, const float* __restrict__ tok,
                             const float* __restrict__ pos, float* __restrict__ x)
{
    int row = blockIdx.x;
    int t   = row % TT;
    int token = ctx[row];
    const float* te = tok + (size_t)token * EE;
    const float* pe = pos + (size_t)t * EE;
    float* xr = x + (size_t)row * EE;
    for (int e = threadIdx.x; e < EE; e += blockDim.x)
        xr[e] = te[e] + pe[e];
}

// ---------------- layernorm (one block per row) ----------------
__global__ void ln_kernel(const float* __restrict__ x, const float* __restrict__ g,
                          const float* __restrict__ b, float* __restrict__ y)
{
    int row = blockIdx.x;
    const float* xr = x + (size_t)row * EE;
    float* yr = y + (size_t)row * EE;
    __shared__ float red[256];
    int tid = threadIdx.x;

    float s = 0.f;
    for (int i = tid; i < EE; i += 256) s += xr[i];
    red[tid] = s; __syncthreads();
    for (int o = 128; o > 0; o >>= 1) { if (tid < o) red[tid] += red[tid + o]; __syncthreads(); }
    float mu = red[0] * (1.0f / EE);
    __syncthreads();

    float v = 0.f;
    for (int i = tid; i < EE; i += 256) { float d = xr[i] - mu; v += d * d; }
    red[tid] = v; __syncthreads();
    for (int o = 128; o > 0; o >>= 1) { if (tid < o) red[tid] += red[tid + o]; __syncthreads(); }
    float rstd = rsqrtf(red[0] * (1.0f / EE) + 1e-5f);

    for (int i = tid; i < EE; i += 256)
        yr[i] = (xr[i] - mu) * rstd * g[i] + b[i];
}

// ---------------- tf32 tensor-core GEMM: C[M,N] = A[M,K] @ W[K,N] ----------------
// BM=128, BN=128, BK=32, 256 threads (8 warps), warp tile 32x64 via m16n8k8 tf32 mma.
// Requires M%128==0, N%128==0, K%32==0.
#define BKC 32
#define ASTRIDE 36
#define BSTRIDE 132

__global__ __launch_bounds__(256, 2) void tgemm_kernel(
    const float* __restrict__ A, const float* __restrict__ W,
    const float* __restrict__ bias, const float* __restrict__ res,
    float* __restrict__ C, int M, int N, int K, int relu)
{
    __shared__ float As[128 * ASTRIDE];   // [m][k], stride 36
    __shared__ float Bs[BKC * BSTRIDE];   // [k][n], stride 132

    int tid  = threadIdx.x;
    int warp = tid >> 5, lane = tid & 31;
    int g = lane >> 2, t = lane & 3;
    int wm = (warp & 3) * 32;
    int wn = (warp >> 2) * 64;
    int row0 = blockIdx.y * 128;
    int col0 = blockIdx.x * 128;

    const float* Ab = A + (size_t)row0 * K;
    const float* Wb = W + col0;

    float acc[2][8][4];
    #pragma unroll
    for (int mi = 0; mi < 2; mi++)
        #pragma unroll
        for (int ni = 0; ni < 8; ni++)
            #pragma unroll
            for (int c = 0; c < 4; c++) acc[mi][ni][c] = 0.f;

    float4 aReg[4], bReg[4];

    // ---- G->reg load for chunk starting at k0 ----
    auto loadG = [&](int k0) {
        #pragma unroll
        for (int i = 0; i < 4; i++) {
            int idx = tid + i * 256;
            int m = idx >> 3, kq = idx & 7;
            aReg[i] = *(const float4*)(Ab + (size_t)m * K + k0 + kq * 4);
            int kr = idx >> 5, nq = idx & 31;
            bReg[i] = *(const float4*)(Wb + (size_t)(k0 + kr) * N + nq * 4);
        }
    };
    // ---- reg->smem store (with tf32 rounding) ----
    auto storeS = [&]() {
        #pragma unroll
        for (int i = 0; i < 4; i++) {
            int idx = tid + i * 256;
            int m = idx >> 3, kq = idx & 7;
            float4 av = aReg[i];
            av.x = f2tf32(av.x); av.y = f2tf32(av.y); av.z = f2tf32(av.z); av.w = f2tf32(av.w);
            *(float4*)&As[m * ASTRIDE + kq * 4] = av;
            int kr = idx >> 5, nq = idx & 31;
            float4 bv = bReg[i];
            bv.x = f2tf32(bv.x); bv.y = f2tf32(bv.y); bv.z = f2tf32(bv.z); bv.w = f2tf32(bv.w);
            *(float4*)&Bs[kr * BSTRIDE + nq * 4] = bv;
        }
    };
    // ---- compute 4 k8-steps on current smem chunk ----
    auto compute = [&]() {
        #pragma unroll
        for (int kk = 0; kk < 4; kk++) {
            int kb = kk * 8;
            uint32_t af[2][4], bf[8][2];
            #pragma unroll
            for (int mi = 0; mi < 2; mi++) {
                int r = wm + mi * 16 + g;
                af[mi][0] = __float_as_uint(As[r * ASTRIDE + kb + t]);
                af[mi][1] = __float_as_uint(As[(r + 8) * ASTRIDE + kb + t]);
                af[mi][2] = __float_as_uint(As[r * ASTRIDE + kb + t + 4]);
                af[mi][3] = __float_as_uint(As[(r + 8) * ASTRIDE + kb + t + 4]);
            }
            #pragma unroll
            for (int ni = 0; ni < 8; ni++) {
                int c = wn + ni * 8 + g;
                bf[ni][0] = __float_as_uint(Bs[(kb + t) * BSTRIDE + c]);
                bf[ni][1] = __float_as_uint(Bs[(kb + t + 4) * BSTRIDE + c]);
            }
            #pragma unroll
            for (int mi = 0; mi < 2; mi++)
                #pragma unroll
                for (int ni = 0; ni < 8; ni++)
                    mma_tf32(acc[mi][ni], af[mi], bf[ni]);
        }
    };

    loadG(0);
    storeS();
    __syncthreads();
    for (int k0 = BKC; k0 < K; k0 += BKC) {
        loadG(k0);
        compute();
        __syncthreads();
        storeS();
        __syncthreads();
    }
    compute();

    // ---- epilogue ----
    #pragma unroll
    for (int mi = 0; mi < 2; mi++) {
        int r = row0 + wm + mi * 16 + g;
        #pragma unroll
        for (int ni = 0; ni < 8; ni++) {
            int c = col0 + wn + ni * 8 + t * 2;
            float v0 = acc[mi][ni][0], v1 = acc[mi][ni][1];
            float v2 = acc[mi][ni][2], v3 = acc[mi][ni][3];
            if (bias) { float b0 = bias[c], b1 = bias[c + 1]; v0 += b0; v1 += b1; v2 += b0; v3 += b1; }
            if (res) {
                v0 += res[(size_t)r * N + c];       v1 += res[(size_t)r * N + c + 1];
                v2 += res[(size_t)(r + 8) * N + c]; v3 += res[(size_t)(r + 8) * N + c + 1];
            }
            if (relu) { v0 = fmaxf(v0, 0.f); v1 = fmaxf(v1, 0.f); v2 = fmaxf(v2, 0.f); v3 = fmaxf(v3, 0.f); }
            *(float2*)&C[(size_t)r * N + c]       = make_float2(v0, v1);
            *(float2*)&C[(size_t)(r + 8) * N + c] = make_float2(v2, v3);
        }
    }
}

// ---------------- attention scores: S[bh,q,k] = (Q.K)/32 ----------------
__global__ __launch_bounds__(256) void attn_scores_kernel(
    const float* __restrict__ q, const float* __restrict__ k, float* __restrict__ att)
{
    int kt = blockIdx.x, qt = blockIdx.y, bh = blockIdx.z;
    if (kt > qt) return;                         // causal pruning at tile level
    int b = bh / HH, h = bh % HH;
    int q0 = qt * 64, k0 = kt * 64;

    __shared__ float Qs[64][65];
    __shared__ float Ks[64][65];
    int tid = threadIdx.x;
    for (int i = tid; i < 64 * 64; i += 256) {
        int r = i >> 6, d = i & 63;
        Qs[r][d] = q[(size_t)(b * TT + q0 + r) * EE + h * 64 + d];
        Ks[r][d] = k[(size_t)(b * TT + k0 + r) * EE + h * 64 + d];
    }
    __syncthreads();

    int tx = tid & 15, ty = tid >> 4;
    float acc[4][4] = {};
    #pragma unroll 4
    for (int d = 0; d < 64; d++) {
        float ar[4], br[4];
        #pragma unroll
        for (int i = 0; i < 4; i++) ar[i] = Qs[ty * 4 + i][d];
        #pragma unroll
        for (int j = 0; j < 4; j++) br[j] = Ks[tx * 4 + j][d];
        #pragma unroll
        for (int i = 0; i < 4; i++)
            #pragma unroll
            for (int j = 0; j < 4; j++) acc[i][j] += ar[i] * br[j];
    }
    const float scale = 0.03125f;  // 1/sqrt(E) = 1/32
    #pragma unroll
    for (int i = 0; i < 4; i++)
        #pragma unroll
        for (int j = 0; j < 4; j++)
            att[((size_t)bh * TT + q0 + ty * 4 + i) * TT + k0 + tx * 4 + j] = acc[i][j] * scale;
}

// ---------------- causal softmax (one block per (bh,q) row) ----------------
__global__ void softmax_kernel(float* __restrict__ att)
{
    int row  = blockIdx.x;          // bh*TT + q
    int qpos = row % TT;
    float* p = att + (size_t)row * TT;
    int n = qpos + 1;
    __shared__ float red[256];
    int tid = threadIdx.x;

    float m = -1e30f;
    for (int i = tid; i < n; i += 256) m = fmaxf(m, p[i]);
    red[tid] = m; __syncthreads();
    for (int o = 128; o > 0; o >>= 1) { if (tid < o) red[tid] = fmaxf(red[tid], red[tid + o]); __syncthreads(); }
    m = red[0]; __syncthreads();

    float s = 0.f;
    for (int i = tid; i < n; i += 256) s += expf(p[i] - m);
    red[tid] = s; __syncthreads();
    for (int o = 128; o > 0; o >>= 1) { if (tid < o) red[tid] += red[tid + o]; __syncthreads(); }
    float inv = 1.f / red[0];

    for (int i = tid; i < n; i += 256) p[i] = expf(p[i] - m) * inv;
    for (int i = n + tid; i < TT; i += 256) p[i] = 0.f;
}

// ---------------- O = P @ V (per (bh, 64-q tile)) ----------------
__global__ __launch_bounds__(256) void attn_o_kernel(
    const float* __restrict__ att, const float* __restrict__ v, float* __restrict__ o)
{
    int qt = blockIdx.x, bh = blockIdx.y;
    int b = bh / HH, h = bh % HH;
    int q0 = qt * 64;

    __shared__ float Ps[64][65];
    __shared__ float Vs[64][65];
    int tid = threadIdx.x, tx = tid & 15, ty = tid >> 4;
    float acc[4][4] = {};

    for (int kt = 0; kt <= qt; kt++) {
        int k0 = kt * 64;
        for (int i = tid; i < 64 * 64; i += 256) {
            int r = i >> 6, c = i & 63;
            Ps[r][c] = att[((size_t)bh * TT + q0 + r) * TT + k0 + c];
            Vs[r][c] = v[(size_t)(b * TT + k0 + r) * EE + h * 64 + c];
        }
        __syncthreads();
        #pragma unroll 4
        for (int kk = 0; kk < 64; kk++) {
            float ar[4], br[4];
            #pragma unroll
            for (int i = 0; i < 4; i++) ar[i] = Ps[ty * 4 + i][kk];
            #pragma unroll
            for (int j = 0; j < 4; j++) br[j] = Vs[kk][tx * 4 + j];
            #pragma unroll
            for (int i = 0; i < 4; i++)
                #pragma unroll
                for (int j = 0; j < 4; j++) acc[i][j] += ar[i] * br[j];
        }
        __syncthreads();
    }
    #pragma unroll
    for (int i = 0; i < 4; i++)
        #pragma unroll
        for (int j = 0; j < 4; j++)
            o[(size_t)(b * TT + q0 + ty * 4 + i) * EE + h * 64 + tx * 4 + j] = acc[i][j];
}

// ---------------- cross-entropy: per-row lse - logit[target] ----------------
__global__ void loss_row_kernel(const float* __restrict__ logits, const int* __restrict__ targets,
                                float* __restrict__ rowloss)
{
    int row = blockIdx.x;
    const float* lr = logits + (size_t)row * VV;
    __shared__ float red[256];
    int tid = threadIdx.x;

    float m = -1e30f;
    for (int i = tid; i < VV; i += 256) m = fmaxf(m, lr[i]);
    red[tid] = m; __syncthreads();
    for (int o = 128; o > 0; o >>= 1) { if (tid < o) red[tid] = fmaxf(red[tid], red[tid + o]); __syncthreads(); }
    m = red[0]; __syncthreads();

    float s = 0.f;
    for (int i = tid; i < VV; i += 256) s += expf(lr[i] - m);
    red[tid] = s; __syncthreads();
    for (int o = 128; o > 0; o >>= 1) { if (tid < o) red[tid] += red[tid + o]; __syncthreads(); }

    if (tid == 0) {
        float lse = m + logf(red[0]);
        rowloss[row] = lse - lr[targets[row]];
    }
}

__global__ void loss_reduce_kernel(const float* __restrict__ rowloss, float* __restrict__ out)
{
    __shared__ float red[256];
    int tid = threadIdx.x;
    float s = 0.f;
    for (int i = tid; i < MROWS; i += 256) s += rowloss[i];
    red[tid] = s; __syncthreads();
    for (int o = 128; o > 0; o >>= 1) { if (tid < o) red[tid] += red[tid + o]; __syncthreads(); }
    if (tid == 0) out[0] = red[0] * (1.0f / MROWS);
}

// ---------------- host orchestration ----------------
extern "C" void kernel_launch(void* const* d_in, const int* in_sizes, int n_in,
                              void* d_out, int out_size)
{
    const int*   ctx  = (const int*)  d_in[0];
    const int*   tgt  = (const int*)  d_in[1];
    const float* tok  = (const float*)d_in[2];
    const float* pos  = (const float*)d_in[3];
    const float* Wq   = (const float*)d_in[4];
    const float* Wk   = (const float*)d_in[5];
    const float* Wv   = (const float*)d_in[6];
    const float* Wo   = (const float*)d_in[7];
    const float* bo   = (const float*)d_in[8];
    const float* ln1g = (const float*)d_in[9];
    const float* ln1b = (const float*)d_in[10];
    const float* ln2g = (const float*)d_in[11];
    const float* ln2b = (const float*)d_in[12];
    const float* W1   = (const float*)d_in[13];
    const float* b1   = (const float*)d_in[14];
    const float* W2   = (const float*)d_in[15];
    const float* b2   = (const float*)d_in[16];
    const float* lnfg = (const float*)d_in[17];
    const float* lnfb = (const float*)d_in[18];
    const float* Wlm  = (const float*)d_in[19];
    const float* blm  = (const float*)d_in[20];

    static float *px = nullptr, *ph, *pq, *pk, *pv, *po, *pff, *patt, *prl;
    if (!px) {
        cudaGetSymbolAddress((void**)&px,  g_x);
        cudaGetSymbolAddress((void**)&ph,  g_h);
        cudaGetSymbolAddress((void**)&pq,  g_q);
        cudaGetSymbolAddress((void**)&pk,  g_k);
        cudaGetSymbolAddress((void**)&pv,  g_v);
        cudaGetSymbolAddress((void**)&po,  g_o);
        cudaGetSymbolAddress((void**)&pff, g_ff);
        cudaGetSymbolAddress((void**)&patt, g_att);
        cudaGetSymbolAddress((void**)&prl, g_rowloss);
    }
    float* out = (float*)d_out;

    embed_kernel<<<MROWS, 256>>>(ctx, tok, pos, px);

    dim3 gE (EE  / 128, MROWS / 128);     // (8,16)
    dim3 gF (FF_ / 128, MROWS / 128);     // (32,16)
    dim3 gV (VV  / 128, MROWS / 128);     // (250,16)
    dim3 gS (TT / 64, TT / 64, BB * HH);  // (16,16,32)
    dim3 gO (TT / 64, BB * HH);           // (16,32)

    for (int l = 0; l < LL; l++) {
        ln_kernel<<<MROWS, 256>>>(px, ln1g + l * EE, ln1b + l * EE, ph);

        tgemm_kernel<<<gE, 256>>>(ph, Wq + (size_t)l * EE * EE, nullptr, nullptr, pq, MROWS, EE, EE, 0);
        tgemm_kernel<<<gE, 256>>>(ph, Wk + (size_t)l * EE * EE, nullptr, nullptr, pk, MROWS, EE, EE, 0);
        tgemm_kernel<<<gE, 256>>>(ph, Wv + (size_t)l * EE * EE, nullptr, nullptr, pv, MROWS, EE, EE, 0);

        attn_scores_kernel<<<gS, 256>>>(pq, pk, patt);
        softmax_kernel<<<BB * HH * TT, 256>>>(patt);
        attn_o_kernel<<<gO, 256>>>(patt, pv, po);

        tgemm_kernel<<<gE, 256>>>(po, Wo + (size_t)l * EE * EE, bo + l * EE, px, px, MROWS, EE, EE, 0);

        ln_kernel<<<MROWS, 256>>>(px, ln2g + l * EE, ln2b + l * EE, ph);
        tgemm_kernel<<<gF, 256>>>(ph, W1 + (size_t)l * EE * FF_, b1 + l * FF_, nullptr, pff, MROWS, FF_, EE, 1);
        tgemm_kernel<<<gE, 256>>>(pff, W2 + (size_t)l * FF_ * EE, b2 + l * EE, px, px, MROWS, EE, FF_, 0);
    }

    ln_kernel<<<MROWS, 256>>>(px, lnfg, lnfb, ph);
    tgemm_kernel<<<gV, 256>>>(ph, Wlm, blm, nullptr, out, MROWS, VV, EE, 0);

    if (out_size > MROWS * VV) {
        loss_row_kernel<<<MROWS, 256>>>(out, tgt, prl);
        loss_reduce_kernel<<<1, 256>>>(prl, out + (size_t)MROWS * VV);
    }
}

// round 3
// speedup vs baseline: 4.2811x; 1.5847x over previous
#include <cuda_runtime.h>
#include <math.h>
#include <stdint.h>

#define BB   2
#define TT   1024
#define EE   1024
#define HH   16
#define HD   64
#define LL   8
#define FF_  4096
#define VV   32000
#define MROWS (BB*TT)          // 2048

// ---------------- scratch ----------------
__device__ float g_x  [MROWS*EE];
__device__ float g_h  [MROWS*EE];
__device__ float g_q  [MROWS*EE];
__device__ float g_k  [MROWS*EE];
__device__ float g_v  [MROWS*EE];
__device__ float g_o  [MROWS*EE];
__device__ float g_ff [MROWS*FF_];
__device__ float g_rowloss[MROWS];

// ---------------- helpers ----------------
__device__ __forceinline__ uint32_t cvt_tf32(float x) {
    uint32_t u;
    asm("cvt.rna.tf32.f32 %0, %1;" : "=r"(u) : "f"(x));
    return u;
}
__device__ __forceinline__ float f2tf32f(float x) { return __uint_as_float(cvt_tf32(x)); }

__device__ __forceinline__ void mma_tf32(float* d, const uint32_t* a, const uint32_t* b) {
    asm volatile(
        "mma.sync.aligned.m16n8k8.row.col.f32.tf32.tf32.f32 "
        "{%0,%1,%2,%3}, {%4,%5,%6,%7}, {%8,%9}, {%0,%1,%2,%3};"
        : "+f"(d[0]), "+f"(d[1]), "+f"(d[2]), "+f"(d[3])
        : "r"(a[0]), "r"(a[1]), "r"(a[2]), "r"(a[3]), "r"(b[0]), "r"(b[1]));
}

__device__ __forceinline__ void cp16(float* s, const float* g) {
    uint32_t sa = (uint32_t)__cvta_generic_to_shared(s);
    asm volatile("cp.async.ca.shared.global [%0], [%1], 16;" :: "r"(sa), "l"(g));
}
#define CP_COMMIT() asm volatile("cp.async.commit_group;")
#define CP_WAIT1()  asm volatile("cp.async.wait_group 1;")

// fast exp on FMA/ALU pipes (MUFU EX2 is only 0.5/cyc/SM)
__device__ __forceinline__ float fexp(float x) {
    float y = fmaxf(x * 1.44269504f, -126.0f);
    float t = y + 12582912.0f;             // round-to-nearest-int trick
    int   e = __float_as_int(t);
    float r = t - 12582912.0f;
    float f = y - r;                        // [-0.5, 0.5]
    float p = 1.0f + f * (0.693147180f + f * (0.240226507f + f * (0.055504109f +
                     f * (0.009618130f + f * 0.001333356f))));
    return __int_as_float((e - 0x4B400000 + 127) << 23) * p;
}

// ---------------- embedding ----------------
__global__ void embed_kernel(const int* __restrict__ ctx, const float* __restrict__ tok,
                             const float* __restrict__ pos, float* __restrict__ x)
{
    int row = blockIdx.x;
    int t   = row % TT;
    int token = ctx[row];
    int tid = threadIdx.x;   // 256 -> one float4 each
    float4 te = ((const float4*)(tok + (size_t)token * EE))[tid];
    float4 pe = ((const float4*)(pos + (size_t)t * EE))[tid];
    float4 o  = make_float4(te.x + pe.x, te.y + pe.y, te.z + pe.z, te.w + pe.w);
    ((float4*)(x + (size_t)row * EE))[tid] = o;
}

// ---------------- layernorm: single-pass, 1 float4/thread ----------------
__global__ void ln_kernel(const float* __restrict__ x, const float* __restrict__ g,
                          const float* __restrict__ b, float* __restrict__ y)
{
    int row = blockIdx.x, tid = threadIdx.x;
    float4 xv = ((const float4*)(x + (size_t)row * EE))[tid];
    float s = xv.x + xv.y + xv.z + xv.w;
    float q = xv.x * xv.x + xv.y * xv.y + xv.z * xv.z + xv.w * xv.w;
    #pragma unroll
    for (int o = 16; o; o >>= 1) {
        s += __shfl_xor_sync(0xffffffffu, s, o);
        q += __shfl_xor_sync(0xffffffffu, q, o);
    }
    __shared__ float ss[8], sq[8];
    int w = tid >> 5;
    if ((tid & 31) == 0) { ss[w] = s; sq[w] = q; }
    __syncthreads();
    if (tid < 32) {
        s = (tid < 8) ? ss[tid] : 0.f;
        q = (tid < 8) ? sq[tid] : 0.f;
        #pragma unroll
        for (int o = 4; o; o >>= 1) {
            s += __shfl_xor_sync(0xffffffffu, s, o);
            q += __shfl_xor_sync(0xffffffffu, q, o);
        }
        if (tid == 0) { ss[0] = s; sq[0] = q; }
    }
    __syncthreads();
    float mu  = ss[0] * (1.0f / EE);
    float var = fmaxf(sq[0] * (1.0f / EE) - mu * mu, 0.f);
    float rs  = rsqrtf(var + 1e-5f);
    float4 gv = ((const float4*)g)[tid], bv = ((const float4*)b)[tid];
    float4 yv;
    yv.x = (xv.x - mu) * rs * gv.x + bv.x;
    yv.y = (xv.y - mu) * rs * gv.y + bv.y;
    yv.z = (xv.z - mu) * rs * gv.z + bv.z;
    yv.w = (xv.w - mu) * rs * gv.w + bv.w;
    ((float4*)(y + (size_t)row * EE))[tid] = yv;
}

// ---------------- tf32 GEMM, cp.async 3-stage, BN=128, BM=WR*32 ----------------
// Supports up to 3 weight/output "chunks" of width wN (for fused QKV).
template<int WR>
__global__ __launch_bounds__(WR*64, 2) void tgemm_kernel(
    const float* __restrict__ A,
    const float* __restrict__ w0, const float* __restrict__ w1, const float* __restrict__ w2,
    int wN,
    const float* __restrict__ bias, const float* __restrict__ res,
    float* c0, float* c1, float* c2,
    int M, int N, int K, int relu)
{
    constexpr int BM = WR * 32;
    constexpr int NT = WR * 64;
    constexpr int BSTR = 136;
    constexpr int ASZ = BM * 36;
    constexpr int BSZ = 32 * BSTR;
    constexpr int ALOADS = BM * 8 / NT;
    constexpr int BLOADS = 1024 / NT;

    extern __shared__ float sm[];
    float* As = sm;
    float* Bs = sm + 3 * ASZ;

    int tid = threadIdx.x;
    int warp = tid >> 5, lane = tid & 31;
    int g = lane >> 2, t = lane & 3;
    int wm = (warp % WR) * 32;
    int wn = (warp / WR) * 64;
    int row0 = blockIdx.y * BM;
    int col0 = blockIdx.x * 128;

    int chunk = col0 / wN;
    int lcol0 = col0 - chunk * wN;
    const float* W = (chunk == 0) ? w0 : (chunk == 1 ? w1 : w2);
    float* C = (chunk == 0) ? c0 : (chunk == 1 ? c1 : c2);

    const float* Ab = A + (size_t)row0 * K;
    const float* Wb = W + lcol0;

    float acc[2][8][4] = {};

    auto issue = [&](int st, int k0) {
        float* as = As + st * ASZ;
        float* bs = Bs + st * BSZ;
        #pragma unroll
        for (int i = 0; i < ALOADS; i++) {
            int idx = tid + i * NT;
            int m = idx >> 3, kq = (idx & 7) * 4;
            cp16(&as[m * 36 + kq], Ab + (size_t)m * K + k0 + kq);
        }
        #pragma unroll
        for (int i = 0; i < BLOADS; i++) {
            int idx = tid + i * NT;
            int kr = idx >> 5, nq = (idx & 31) * 4;
            cp16(&bs[kr * BSTR + nq], Wb + (size_t)(k0 + kr) * wN + nq);
        }
    };
    auto compute = [&](int st) {
        const float* as = As + st * ASZ;
        const float* bs = Bs + st * BSZ;
        #pragma unroll
        for (int kk = 0; kk < 4; kk++) {
            int kb = kk * 8;
            uint32_t af[2][4], bf[8][2];
            #pragma unroll
            for (int mi = 0; mi < 2; mi++) {
                int r = wm + mi * 16 + g;
                af[mi][0] = cvt_tf32(as[r * 36 + kb + t]);
                af[mi][1] = cvt_tf32(as[(r + 8) * 36 + kb + t]);
                af[mi][2] = cvt_tf32(as[r * 36 + kb + t + 4]);
                af[mi][3] = cvt_tf32(as[(r + 8) * 36 + kb + t + 4]);
            }
            #pragma unroll
            for (int ni = 0; ni < 8; ni++) {
                int c = wn + ni * 8 + g;
                bf[ni][0] = cvt_tf32(bs[(kb + t) * BSTR + c]);
                bf[ni][1] = cvt_tf32(bs[(kb + t + 4) * BSTR + c]);
            }
            #pragma unroll
            for (int mi = 0; mi < 2; mi++)
                #pragma unroll
                for (int ni = 0; ni < 8; ni++)
                    mma_tf32(acc[mi][ni], af[mi], bf[ni]);
        }
    };

    issue(0, 0);  CP_COMMIT();
    issue(1, 32); CP_COMMIT();
    int s = 0;
    for (int k0 = 0; k0 < K; k0 += 32) {
        CP_WAIT1();
        __syncthreads();
        int kpf = k0 + 64;
        if (kpf < K) issue((s + 2) % 3, kpf);
        CP_COMMIT();
        compute(s);
        s = (s + 1) % 3;
        __syncthreads();
    }

    #pragma unroll
    for (int mi = 0; mi < 2; mi++) {
        int r = row0 + wm + mi * 16 + g;
        #pragma unroll
        for (int ni = 0; ni < 8; ni++) {
            int c = lcol0 + wn + ni * 8 + t * 2;
            float v0 = acc[mi][ni][0], v1 = acc[mi][ni][1];
            float v2 = acc[mi][ni][2], v3 = acc[mi][ni][3];
            if (bias) { float b0 = bias[c], b1 = bias[c + 1]; v0 += b0; v1 += b1; v2 += b0; v3 += b1; }
            if (res) {
                v0 += res[(size_t)r * wN + c];       v1 += res[(size_t)r * wN + c + 1];
                v2 += res[(size_t)(r + 8) * wN + c]; v3 += res[(size_t)(r + 8) * wN + c + 1];
            }
            if (relu) { v0 = fmaxf(v0, 0.f); v1 = fmaxf(v1, 0.f); v2 = fmaxf(v2, 0.f); v3 = fmaxf(v3, 0.f); }
            *(float2*)&C[(size_t)r * wN + c]       = make_float2(v0, v1);
            *(float2*)&C[(size_t)(r + 8) * wN + c] = make_float2(v2, v3);
        }
    }
}

// ---------------- fused flash attention (causal, HD=64, scale=1/32) ----------------
#define PQ 68
#define PV 72
__global__ __launch_bounds__(128, 3) void flash_kernel(
    const float* __restrict__ q, const float* __restrict__ k,
    const float* __restrict__ v, float* __restrict__ o)
{
    extern __shared__ float sm[];
    float* Qs = sm;               // 64 x PQ
    float* Ks = Qs + 64 * PQ;     // 64 x PQ
    float* Ps = Ks + 64 * PQ;     // 64 x PQ
    float* Vs = Ps + 64 * PQ;     // 64 x PV

    int qt = blockIdx.x, bh = blockIdx.y;
    int b = bh >> 4, h = bh & 15;
    int q0 = qt * 64;

    int tid = threadIdx.x;
    int warp = tid >> 5, lane = tid & 31;
    int g = lane >> 2, t = lane & 3;
    int wq = warp * 16;
    int r0 = wq + g, r1 = wq + g + 8;

    // load Q tile once (tf32)
    for (int i = tid; i < 1024; i += 128) {
        int r = i >> 4, d = (i & 15) * 4;
        float4 x = *(const float4*)(q + (size_t)(b * TT + q0 + r) * EE + h * 64 + d);
        *(float4*)&Qs[r * PQ + d] = make_float4(f2tf32f(x.x), f2tf32f(x.y), f2tf32f(x.z), f2tf32f(x.w));
    }

    float accO[8][4] = {};
    float mr0 = -1e30f, mr1 = -1e30f, lr0 = 0.f, lr1 = 0.f;
    const float scale = 0.03125f;   // 1/sqrt(E)

    for (int kt = 0; kt <= qt; kt++) {
        int k0 = kt * 64;
        __syncthreads();
        for (int i = tid; i < 1024; i += 128) {
            int r = i >> 4, d = (i & 15) * 4;
            float4 xk = *(const float4*)(k + (size_t)(b * TT + k0 + r) * EE + h * 64 + d);
            *(float4*)&Ks[r * PQ + d] = make_float4(f2tf32f(xk.x), f2tf32f(xk.y), f2tf32f(xk.z), f2tf32f(xk.w));
            float4 xv = *(const float4*)(v + (size_t)(b * TT + k0 + r) * EE + h * 64 + d);
            *(float4*)&Vs[r * PV + d] = make_float4(f2tf32f(xv.x), f2tf32f(xv.y), f2tf32f(xv.z), f2tf32f(xv.w));
        }
        __syncthreads();

        // S = Q K^T (warp: 16 rows x 64 cols)
        float accS[8][4] = {};
        #pragma unroll
        for (int kb = 0; kb < 64; kb += 8) {
            uint32_t af[4];
            af[0] = __float_as_uint(Qs[r0 * PQ + kb + t]);
            af[1] = __float_as_uint(Qs[r1 * PQ + kb + t]);
            af[2] = __float_as_uint(Qs[r0 * PQ + kb + t + 4]);
            af[3] = __float_as_uint(Qs[r1 * PQ + kb + t + 4]);
            #pragma unroll
            for (int ni = 0; ni < 8; ni++) {
                uint32_t bf[2];
                bf[0] = __float_as_uint(Ks[(ni * 8 + g) * PQ + kb + t]);
                bf[1] = __float_as_uint(Ks[(ni * 8 + g) * PQ + kb + t + 4]);
                mma_tf32(accS[ni], af, bf);
            }
        }

        // scale + causal mask (diag tile only)
        bool diag = (kt == qt);
        #pragma unroll
        for (int ni = 0; ni < 8; ni++) {
            int c = ni * 8 + t * 2;
            accS[ni][0] *= scale; accS[ni][1] *= scale;
            accS[ni][2] *= scale; accS[ni][3] *= scale;
            if (diag) {
                if (c     > r0) accS[ni][0] = -1e30f;
                if (c + 1 > r0) accS[ni][1] = -1e30f;
                if (c     > r1) accS[ni][2] = -1e30f;
                if (c + 1 > r1) accS[ni][3] = -1e30f;
            }
        }

        // row max
        float m0 = -1e30f, m1 = -1e30f;
        #pragma unroll
        for (int ni = 0; ni < 8; ni++) {
            m0 = fmaxf(m0, fmaxf(accS[ni][0], accS[ni][1]));
            m1 = fmaxf(m1, fmaxf(accS[ni][2], accS[ni][3]));
        }
        m0 = fmaxf(m0, __shfl_xor_sync(0xffffffffu, m0, 1));
        m0 = fmaxf(m0, __shfl_xor_sync(0xffffffffu, m0, 2));
        m1 = fmaxf(m1, __shfl_xor_sync(0xffffffffu, m1, 1));
        m1 = fmaxf(m1, __shfl_xor_sync(0xffffffffu, m1, 2));

        float mn0 = fmaxf(mr0, m0), mn1 = fmaxf(mr1, m1);
        float a0 = fexp(mr0 - mn0), a1 = fexp(mr1 - mn1);

        float s0 = 0.f, s1 = 0.f;
        #pragma unroll
        for (int ni = 0; ni < 8; ni++) {
            accS[ni][0] = fexp(accS[ni][0] - mn0);
            accS[ni][1] = fexp(accS[ni][1] - mn0);
            accS[ni][2] = fexp(accS[ni][2] - mn1);
            accS[ni][3] = fexp(accS[ni][3] - mn1);
            s0 += accS[ni][0] + accS[ni][1];
            s1 += accS[ni][2] + accS[ni][3];
        }
        s0 += __shfl_xor_sync(0xffffffffu, s0, 1);
        s0 += __shfl_xor_sync(0xffffffffu, s0, 2);
        s1 += __shfl_xor_sync(0xffffffffu, s1, 1);
        s1 += __shfl_xor_sync(0xffffffffu, s1, 2);

        lr0 = lr0 * a0 + s0;
        lr1 = lr1 * a1 + s1;
        mr0 = mn0; mr1 = mn1;

        #pragma unroll
        for (int ni = 0; ni < 8; ni++) {
            accO[ni][0] *= a0; accO[ni][1] *= a0;
            accO[ni][2] *= a1; accO[ni][3] *= a1;
        }

        // P -> smem (tf32), own rows only
        #pragma unroll
        for (int ni = 0; ni < 8; ni++) {
            int c = ni * 8 + t * 2;
            Ps[r0 * PQ + c]     = f2tf32f(accS[ni][0]);
            Ps[r0 * PQ + c + 1] = f2tf32f(accS[ni][1]);
            Ps[r1 * PQ + c]     = f2tf32f(accS[ni][2]);
            Ps[r1 * PQ + c + 1] = f2tf32f(accS[ni][3]);
        }
        __syncwarp();

        // O += P V
        #pragma unroll
        for (int kb = 0; kb < 64; kb += 8) {
            uint32_t af[4];
            af[0] = __float_as_uint(Ps[r0 * PQ + kb + t]);
            af[1] = __float_as_uint(Ps[r1 * PQ + kb + t]);
            af[2] = __float_as_uint(Ps[r0 * PQ + kb + t + 4]);
            af[3] = __float_as_uint(Ps[r1 * PQ + kb + t + 4]);
            #pragma unroll
            for (int ni = 0; ni < 8; ni++) {
                uint32_t bf[2];
                bf[0] = __float_as_uint(Vs[(kb + t) * PV + ni * 8 + g]);
                bf[1] = __float_as_uint(Vs[(kb + t + 4) * PV + ni * 8 + g]);
                mma_tf32(accO[ni], af, bf);
            }
        }
    }

    float i0 = 1.f / lr0, i1 = 1.f / lr1;
    #pragma unroll
    for (int ni = 0; ni < 8; ni++) {
        int d = ni * 8 + t * 2;
        *(float2*)(o + (size_t)(b * TT + q0 + r0) * EE + h * 64 + d) =
            make_float2(accO[ni][0] * i0, accO[ni][1] * i0);
        *(float2*)(o + (size_t)(b * TT + q0 + r1) * EE + h * 64 + d) =
            make_float2(accO[ni][2] * i1, accO[ni][3] * i1);
    }
}

// ---------------- cross-entropy ----------------
__global__ void loss_row_kernel(const float* __restrict__ logits, const int* __restrict__ targets,
                                float* __restrict__ rowloss)
{
    int row = blockIdx.x;
    const float* lr = logits + (size_t)row * VV;
    __shared__ float red[256];
    int tid = threadIdx.x;

    float m = -1e30f;
    for (int i = tid; i < VV; i += 256) m = fmaxf(m, lr[i]);
    red[tid] = m; __syncthreads();
    for (int o = 128; o > 0; o >>= 1) { if (tid < o) red[tid] = fmaxf(red[tid], red[tid + o]); __syncthreads(); }
    m = red[0]; __syncthreads();

    float s = 0.f;
    for (int i = tid; i < VV; i += 256) s += expf(lr[i] - m);
    red[tid] = s; __syncthreads();
    for (int o = 128; o > 0; o >>= 1) { if (tid < o) red[tid] += red[tid + o]; __syncthreads(); }

    if (tid == 0) {
        float lse = m + logf(red[0]);
        rowloss[row] = lse - lr[targets[row]];
    }
}

__global__ void loss_reduce_kernel(const float* __restrict__ rowloss, float* __restrict__ out)
{
    __shared__ float red[256];
    int tid = threadIdx.x;
    float s = 0.f;
    for (int i = tid; i < MROWS; i += 256) s += rowloss[i];
    red[tid] = s; __syncthreads();
    for (int o = 128; o > 0; o >>= 1) { if (tid < o) red[tid] += red[tid + o]; __syncthreads(); }
    if (tid == 0) out[0] = red[0] * (1.0f / MROWS);
}

// ---------------- host orchestration ----------------
#define SMEM4 (3 * (128*36 + 32*136) * 4)   // 107520
#define SMEM2 (3 * (64*36 + 32*136) * 4)    // 79872
#define SMEMF ((3*64*PQ + 64*PV) * 4)       // 70656

extern "C" void kernel_launch(void* const* d_in, const int* in_sizes, int n_in,
                              void* d_out, int out_size)
{
    const int*   ctx  = (const int*)  d_in[0];
    const int*   tgt  = (const int*)  d_in[1];
    const float* tok  = (const float*)d_in[2];
    const float* pos  = (const float*)d_in[3];
    const float* Wq   = (const float*)d_in[4];
    const float* Wk   = (const float*)d_in[5];
    const float* Wv   = (const float*)d_in[6];
    const float* Wo   = (const float*)d_in[7];
    const float* bo   = (const float*)d_in[8];
    const float* ln1g = (const float*)d_in[9];
    const float* ln1b = (const float*)d_in[10];
    const float* ln2g = (const float*)d_in[11];
    const float* ln2b = (const float*)d_in[12];
    const float* W1   = (const float*)d_in[13];
    const float* b1   = (const float*)d_in[14];
    const float* W2   = (const float*)d_in[15];
    const float* b2   = (const float*)d_in[16];
    const float* lnfg = (const float*)d_in[17];
    const float* lnfb = (const float*)d_in[18];
    const float* Wlm  = (const float*)d_in[19];
    const float* blm  = (const float*)d_in[20];

    static float *px = nullptr, *ph, *pq, *pk, *pv, *po, *pff, *prl;
    if (!px) {
        cudaGetSymbolAddress((void**)&px,  g_x);
        cudaGetSymbolAddress((void**)&ph,  g_h);
        cudaGetSymbolAddress((void**)&pq,  g_q);
        cudaGetSymbolAddress((void**)&pk,  g_k);
        cudaGetSymbolAddress((void**)&pv,  g_v);
        cudaGetSymbolAddress((void**)&po,  g_o);
        cudaGetSymbolAddress((void**)&pff, g_ff);
        cudaGetSymbolAddress((void**)&prl, g_rowloss);
    }
    cudaFuncSetAttribute(tgemm_kernel<4>, cudaFuncAttributeMaxDynamicSharedMemorySize, SMEM4);
    cudaFuncSetAttribute(tgemm_kernel<2>, cudaFuncAttributeMaxDynamicSharedMemorySize, SMEM2);
    cudaFuncSetAttribute(flash_kernel,    cudaFuncAttributeMaxDynamicSharedMemorySize, SMEMF);

    float* out = (float*)d_out;

    embed_kernel<<<MROWS, 256>>>(ctx, tok, pos, px);

    dim3 gQKV(24, 16);     // N=3072, BM=128
    dim3 gEo (8, 32);      // N=1024, BM=64
    dim3 gF1 (32, 16);     // N=4096, BM=128
    dim3 gLM (250, 16);    // N=32000, BM=128
    dim3 gFA (16, 32);     // (q tiles, B*H)

    for (int l = 0; l < LL; l++) {
        size_t oE = (size_t)l * EE * EE, oF1 = (size_t)l * EE * FF_, oF2 = (size_t)l * FF_ * EE;

        ln_kernel<<<MROWS, 256>>>(px, ln1g + l * EE, ln1b + l * EE, ph);

        tgemm_kernel<4><<<gQKV, 256, SMEM4>>>(ph, Wq + oE, Wk + oE, Wv + oE, EE,
                                              nullptr, nullptr, pq, pk, pv,
                                              MROWS, 3 * EE, EE, 0);

        flash_kernel<<<gFA, 128, SMEMF>>>(pq, pk, pv, po);

        tgemm_kernel<2><<<gEo, 128, SMEM2>>>(po, Wo + oE, Wo + oE, Wo + oE, EE,
                                             bo + l * EE, px, px, px, px,
                                             MROWS, EE, EE, 0);

        ln_kernel<<<MROWS, 256>>>(px, ln2g + l * EE, ln2b + l * EE, ph);

        tgemm_kernel<4><<<gF1, 256, SMEM4>>>(ph, W1 + oF1, W1 + oF1, W1 + oF1, FF_,
                                             b1 + l * FF_, nullptr, pff, pff, pff,
                                             MROWS, FF_, EE, 1);

        tgemm_kernel<2><<<gEo, 128, SMEM2>>>(pff, W2 + oF2, W2 + oF2, W2 + oF2, EE,
                                             b2 + l * EE, px, px, px, px,
                                             MROWS, EE, FF_, 0);
    }

    ln_kernel<<<MROWS, 256>>>(px, lnfg, lnfb, ph);
    tgemm_kernel<4><<<gLM, 256, SMEM4>>>(ph, Wlm, Wlm, Wlm, VV,
                                         blm, nullptr, out, out, out,
                                         MROWS, VV, EE, 0);

    if (out_size > MROWS * VV) {
        loss_row_kernel<<<MROWS, 256>>>(out, tgt, prl);
        loss_reduce_kernel<<<1, 256>>>(prl, out + (size_t)MROWS * VV);
    }
}